// round 3
// baseline (speedup 1.0000x reference)
#include <cuda_runtime.h>
#include <cuda_bf16.h>
#include <cstdint>
#include <cstddef>

// ----- problem dims -----
#define MDIM 8192
#define NDIM 16384
#define KDIM 4096

// ----- tiling -----
#define BM 128
#define BN 128
#define KC 32
#define NUM_KITER (KDIM / KC)      // 128
#define TILES_M (MDIM / BM)        // 64
#define TILES_N (NDIM / BN)        // 128
#define NCTA (TILES_M * TILES_N)   // 8192
#define GROUP_M 8

// padded smem row: 32 bf16 = 64B, padded to 80B (conflict-free ldmatrix)
#define ROWB 80
#define ARR_BYTES (128 * ROWB)     // 10240
#define AHI_OFF 0
#define ALO_OFF ARR_BYTES
#define B_OFF   (2 * ARR_BYTES)
#define STAGE_BYTES (3 * ARR_BYTES)   // 30720
#define NSTAGE 3
#define SMEM_TOTAL (NSTAGE * STAGE_BYTES)  // 92160

// ----- device scratch -----
__device__ __align__(256) __nv_bfloat16 g_wbf[(size_t)NDIM * KDIM];   // 128 MB
__device__ __align__(256) __nv_bfloat16 g_xhi[(size_t)MDIM * KDIM];   //  64 MB
__device__ __align__(256) __nv_bfloat16 g_xlo[(size_t)MDIM * KDIM];   //  64 MB

// ----- helpers -----
__device__ __forceinline__ uint32_t smem_u32(const void* p) {
    uint32_t a;
    asm("{ .reg .u64 t; cvta.to.shared.u64 t, %1; cvt.u32.u64 %0, t; }" : "=r"(a) : "l"(p));
    return a;
}
__device__ __forceinline__ void cp16(uint32_t dst, const void* src) {
    asm volatile("cp.async.cg.shared.global [%0], [%1], 16;"
                 :: "r"(dst), "l"(__cvta_generic_to_global(src)) : "memory");
}
__device__ __forceinline__ void ldsm4(uint32_t& r0, uint32_t& r1, uint32_t& r2, uint32_t& r3,
                                      uint32_t addr) {
    asm volatile("ldmatrix.sync.aligned.m8n8.x4.shared.b16 {%0,%1,%2,%3}, [%4];"
                 : "=r"(r0), "=r"(r1), "=r"(r2), "=r"(r3) : "r"(addr));
}
__device__ __forceinline__ void mma16816(float* c, const uint32_t* a, const uint32_t* b) {
    asm volatile(
        "mma.sync.aligned.m16n8k16.row.col.f32.bf16.bf16.f32 "
        "{%0,%1,%2,%3}, {%4,%5,%6,%7}, {%8,%9}, {%0,%1,%2,%3};"
        : "+f"(c[0]), "+f"(c[1]), "+f"(c[2]), "+f"(c[3])
        : "r"(a[0]), "r"(a[1]), "r"(a[2]), "r"(a[3]), "r"(b[0]), "r"(b[1]));
}

// ----- preprocessing: Wq int32 -> bf16 (exact, |q|<=127) -----
__global__ void __launch_bounds__(256) k_wconv(const int4* __restrict__ wq) {
    size_t i = (size_t)blockIdx.x * 256 + threadIdx.x;
    int4 v = wq[i];
    union { __nv_bfloat16 h[4]; uint2 u; } o;
    o.h[0] = __float2bfloat16_rn((float)v.x);
    o.h[1] = __float2bfloat16_rn((float)v.y);
    o.h[2] = __float2bfloat16_rn((float)v.z);
    o.h[3] = __float2bfloat16_rn((float)v.w);
    ((uint2*)g_wbf)[i] = o.u;
}

// ----- preprocessing: x fp32 -> hi/lo bf16 split -----
__global__ void __launch_bounds__(256) k_xconv(const float4* __restrict__ x) {
    size_t i = (size_t)blockIdx.x * 256 + threadIdx.x;
    float4 v = x[i];
    union { __nv_bfloat16 h[4]; uint2 u; } hi, lo;
    hi.h[0] = __float2bfloat16_rn(v.x); lo.h[0] = __float2bfloat16_rn(v.x - __bfloat162float(hi.h[0]));
    hi.h[1] = __float2bfloat16_rn(v.y); lo.h[1] = __float2bfloat16_rn(v.y - __bfloat162float(hi.h[1]));
    hi.h[2] = __float2bfloat16_rn(v.z); lo.h[2] = __float2bfloat16_rn(v.z - __bfloat162float(hi.h[2]));
    hi.h[3] = __float2bfloat16_rn(v.w); lo.h[3] = __float2bfloat16_rn(v.w - __bfloat162float(hi.h[3]));
    ((uint2*)g_xhi)[i] = hi.u;
    ((uint2*)g_xlo)[i] = lo.u;
}

// ----- cp.async one K-chunk (KC=32) into a stage -----
// 128 rows x 64B per array; thread t: row=t>>1, two 16B chunks
__device__ __forceinline__ void load_chunk(uint32_t stage, int tm, int tn, int kk, int tid) {
    int row  = tid >> 1;
    int cb   = (tid & 1) * 32;           // byte offset of first chunk
    int ce   = (tid & 1) * 16;           // element offset
    const __nv_bfloat16* xhi = g_xhi + ((size_t)(tm * BM + row)) * KDIM + kk + ce;
    const __nv_bfloat16* xlo = g_xlo + ((size_t)(tm * BM + row)) * KDIM + kk + ce;
    const __nv_bfloat16* wb  = g_wbf + ((size_t)(tn * BN + row)) * KDIM + kk + ce;
    uint32_t so = stage + (uint32_t)(row * ROWB + cb);
    cp16(so + AHI_OFF,      xhi);     cp16(so + AHI_OFF + 16, xhi + 8);
    cp16(so + ALO_OFF,      xlo);     cp16(so + ALO_OFF + 16, xlo + 8);
    cp16(so + B_OFF,        wb);      cp16(so + B_OFF + 16,   wb + 8);
}

// ----- main GEMM: 128x128 tile, mma.sync bf16 hi/lo, fp32 accum -----
__global__ void __launch_bounds__(256, 2) k_gemm(const float* __restrict__ scale,
                                                 const float* __restrict__ bias,
                                                 float* __restrict__ out) {
    extern __shared__ char smem[];
    uint32_t sbase = smem_u32(smem);
    int tid = threadIdx.x, wid = tid >> 5, lane = tid & 31;

    // grouped rasterization
    int bid   = blockIdx.x;
    int group = bid / (GROUP_M * TILES_N);
    int rem   = bid % (GROUP_M * TILES_N);
    int tm    = group * GROUP_M + (rem % GROUP_M);
    int tn    = rem / GROUP_M;

    int wm = wid & 3;       // M sub-block (32 rows)
    int wn = wid >> 2;      // N sub-block (64 cols)

    float acc[2][8][4];
#pragma unroll
    for (int i = 0; i < 2; i++)
#pragma unroll
        for (int j = 0; j < 8; j++)
#pragma unroll
            for (int k = 0; k < 4; k++) acc[i][j][k] = 0.f;

    // prologue: stage 0, 1
    load_chunk(sbase, tm, tn, 0, tid);
    asm volatile("cp.async.commit_group;" ::: "memory");
    load_chunk(sbase + STAGE_BYTES, tm, tn, KC, tid);
    asm volatile("cp.async.commit_group;" ::: "memory");

    // per-lane ldmatrix address components (byte offsets within an array)
    int a_row = wm * 32 + (lane & 15);             // + mfrag*16
    int a_col = (lane >> 4) * 16;                  // + ks*32
    int b_row = wn * 64 + ((lane >> 4) & 1) * 8 + (lane & 7);   // + nf2*16
    int b_col = ((lane >> 3) & 1) * 16;            // + ks*32

    int stg = 0;
#pragma unroll 1
    for (int i = 0; i < NUM_KITER; i++) {
        asm volatile("cp.async.wait_group 1;" ::: "memory");
        __syncthreads();
        uint32_t cur = sbase + (uint32_t)stg * STAGE_BYTES;

        // prefetch chunk i+2
        if (i + 2 < NUM_KITER) {
            int ns = stg + 2; if (ns >= NSTAGE) ns -= NSTAGE;
            load_chunk(sbase + (uint32_t)ns * STAGE_BYTES, tm, tn, (i + 2) * KC, tid);
        }
        asm volatile("cp.async.commit_group;" ::: "memory");

#pragma unroll
        for (int ks = 0; ks < 2; ks++) {
            uint32_t ahi[2][4], alo[2][4], bf[8][2];
#pragma unroll
            for (int mf = 0; mf < 2; mf++) {
                uint32_t aaddr = cur + (uint32_t)((a_row + mf * 16) * ROWB + a_col + ks * 32);
                ldsm4(ahi[mf][0], ahi[mf][1], ahi[mf][2], ahi[mf][3], aaddr + AHI_OFF);
                ldsm4(alo[mf][0], alo[mf][1], alo[mf][2], alo[mf][3], aaddr + ALO_OFF);
            }
#pragma unroll
            for (int nf2 = 0; nf2 < 4; nf2++) {
                uint32_t baddr = cur + B_OFF +
                    (uint32_t)((b_row + nf2 * 16) * ROWB + b_col + ks * 32);
                ldsm4(bf[nf2 * 2][0], bf[nf2 * 2][1], bf[nf2 * 2 + 1][0], bf[nf2 * 2 + 1][1],
                      baddr);
            }
#pragma unroll
            for (int mf = 0; mf < 2; mf++)
#pragma unroll
                for (int nf = 0; nf < 8; nf++) {
                    mma16816(acc[mf][nf], ahi[mf], bf[nf]);
                    mma16816(acc[mf][nf], alo[mf], bf[nf]);
                }
        }
        stg = stg + 1; if (stg >= NSTAGE) stg = 0;
    }

    // ----- epilogue: y = acc * scale[n] + bias[n] -----
    int n_base = tn * BN + wn * 64 + (lane & 3) * 2;
    float sc[8][2], bi[8][2];
#pragma unroll
    for (int nf = 0; nf < 8; nf++) {
        int n = n_base + nf * 8;
        sc[nf][0] = scale[n];     sc[nf][1] = scale[n + 1];
        bi[nf][0] = bias[n];      bi[nf][1] = bias[n + 1];
    }
    int m_base = tm * BM + wm * 32 + (lane >> 2);
#pragma unroll
    for (int mf = 0; mf < 2; mf++) {
#pragma unroll
        for (int half = 0; half < 2; half++) {
            size_t row = (size_t)(m_base + mf * 16 + half * 8);
            float* orow = out + row * NDIM + n_base;
#pragma unroll
            for (int nf = 0; nf < 8; nf++) {
                float2 v;
                v.x = acc[mf][nf][half * 2 + 0] * sc[nf][0] + bi[nf][0];
                v.y = acc[mf][nf][half * 2 + 1] * sc[nf][1] + bi[nf][1];
                *(float2*)(orow + nf * 8) = v;
            }
        }
    }
}

extern "C" void kernel_launch(void* const* d_in, const int* in_sizes, int n_in,
                              void* d_out, int out_size) {
    const float* x     = (const float*)d_in[0];
    const int*   wq    = (const int*)d_in[1];
    const float* scale = (const float*)d_in[2];
    const float* bias  = (const float*)d_in[3];
    float* out = (float*)d_out;

    k_wconv<<<(int)(((size_t)NDIM * KDIM) / (256 * 4)), 256>>>((const int4*)wq);
    k_xconv<<<(int)(((size_t)MDIM * KDIM) / (256 * 4)), 256>>>((const float4*)x);

    cudaFuncSetAttribute(k_gemm, cudaFuncAttributeMaxDynamicSharedMemorySize, SMEM_TOTAL);
    k_gemm<<<NCTA, 256, SMEM_TOTAL>>>(scale, bias, out);
}